// round 5
// baseline (speedup 1.0000x reference)
#include <cuda_runtime.h>

#define IMG     512
#define WSTRIP  128
#define HSEG    128
#define HALO    5
#define SROW    138

typedef unsigned long long u64;

static __device__ __forceinline__ u64 pk(float lo, float hi) {
    u64 r; asm("mov.b64 %0, {%1, %2};" : "=l"(r) : "f"(lo), "f"(hi)); return r;
}
static __device__ __forceinline__ void upk(u64 v, float& lo, float& hi) {
    asm("mov.b64 {%0, %1}, %2;" : "=f"(lo), "=f"(hi) : "l"(v));
}
static __device__ __forceinline__ u64 fma2(u64 a, u64 b, u64 c) {
    u64 d; asm("fma.rn.f32x2 %0, %1, %2, %3;" : "=l"(d) : "l"(a), "l"(b), "l"(c)); return d;
}
static __device__ __forceinline__ u64 mul2(u64 a, u64 b) {
    u64 d; asm("mul.rn.f32x2 %0, %1, %2;" : "=l"(d) : "l"(a), "l"(b)); return d;
}

#define NROW (11 * SROW)               // u64s per buffer
#define IDX(b, p, c) (((b) * 11 + (p)) * SROW + (c))

__global__ void __launch_bounds__(128, 3)
ssim_fused_kernel(const float* __restrict__ A, const float* __restrict__ B,
                  const float* __restrict__ F, float* __restrict__ out,
                  float scale)
{
    constexpr float W[11] = {0.00102838f, 0.00759876f, 0.03600077f, 0.10936069f,
                             0.21300553f, 0.26601172f, 0.21300553f, 0.10936069f,
                             0.03600077f, 0.00759876f, 0.00102838f};
    constexpr float C1 = 0.0001f, C2 = 0.0009f;

    extern __shared__ u64 dsm[];
    u64* sAB = dsm;                    // (a, b)
    u64* sFQ = dsm + 2 * NROW;         // (f, f*f)
    u64* sAF = dsm + 4 * NROW;         // (a*f, b*f)
    float* wpart = (float*)(dsm + 6 * NROW);

    const int t  = threadIdx.x;
    const int x0 = blockIdx.x * WSTRIP;
    const int y0 = blockIdx.y * HSEG;
    const int y1 = y0 + HSEG;
    const size_t poff = (size_t)blockIdx.z * (size_t)(IMG * IMG);
    const float* ga = A + poff;
    const float* gb = B + poff;
    const float* gf = F + poff;

    u64 W2[6];
#pragma unroll
    for (int j = 0; j < 6; ++j) W2[j] = pk(W[j], W[j]);

    // vertical ring: 4 packed channels x 11 pending output rows
    u64 aAB[11], aAB2[11], aABF[11], aFF[11];
#pragma unroll
    for (int s = 0; s < 11; ++s) { aAB[s] = 0; aAB2[s] = 0; aABF[s] = 0; aFF[s] = 0; }

    float ssum = 0.0f;

    const int ract_lo = (y0 - HALO) < 0 ? 0 : (y0 - HALO);
    const int ract_hi = (y1 + HALO - 1) > (IMG - 1) ? (IMG - 1) : (y1 + HALO - 1);

    const int  c0  = x0 - HALO + t;
    const bool c0v = (c0 >= 0) && (c0 < IMG);
    const int  c1  = c0 + 128;
    const bool c1v = (t < 10) && (c1 < IMG);

    const int base    = ((y0 - HALO + 11) / 11) * 11 - 11;   // multiple of 11 <= y0-5
    const int nchunks = (y1 + HALO - base + 10) / 11;

    // ---- prologue: stage rows base..base+10 into buffer 0 ----
#pragma unroll
    for (int p = 0; p < 11; ++p) {
        const int r = base + p;
        float va = 0, vb = 0, vf = 0, ua = 0, ub = 0, uf = 0;
        if (r >= ract_lo && r <= ract_hi) {
            if (c0v) { const int i = r * IMG + c0; va = ga[i]; vb = gb[i]; vf = gf[i]; }
            if (c1v) { const int i = r * IMG + c1; ua = ga[i]; ub = gb[i]; uf = gf[i]; }
        }
        sAB[IDX(0, p, t)] = pk(va, vb);
        sFQ[IDX(0, p, t)] = pk(vf, vf * vf);
        sAF[IDX(0, p, t)] = pk(va * vf, vb * vf);
        if (t < 10) {
            sAB[IDX(0, p, t + 128)] = pk(ua, ub);
            sFQ[IDX(0, p, t + 128)] = pk(uf, uf * uf);
            sAF[IDX(0, p, t + 128)] = pk(ua * uf, ub * uf);
        }
    }
    __syncthreads();

#pragma unroll 1
    for (int chk = 0; chk < nchunks; ++chk) {
        const int rbase = base + chk * 11;
        const int bb = chk & 1, nb = bb ^ 1;
#pragma unroll
        for (int p = 0; p < 11; ++p) {
            const int row = rbase + p;

            // issue global loads for row+11 (next chunk, same phase slot)
            const int nr = row + 11;
            float va = 0, vb = 0, vf = 0, ua = 0, ub = 0, uf = 0;
            if (nr >= ract_lo && nr <= ract_hi) {
                if (c0v) { const int i = nr * IMG + c0; va = ga[i]; vb = gb[i]; vf = gf[i]; }
                if (c1v) { const int i = nr * IMG + c1; ua = ga[i]; ub = gb[i]; uf = gf[i]; }
            }

            if (row >= ract_lo && row <= ract_hi) {
                const u64* rab = sAB + IDX(bb, p, t);
                const u64* rfq = sFQ + IDX(bb, p, t);
                const u64* raf = sAF + IDX(bb, p, t);
                u64 hAB = 0, hAB2 = 0, hABF = 0, hFF = 0;
#pragma unroll
                for (int j = 0; j < 11; ++j) {
                    const u64 w2  = W2[j < 6 ? j : 10 - j];
                    const u64 vab = rab[j];
                    hAB  = fma2(vab, w2, hAB);          // (Sa, Sb)
                    const u64 t1 = mul2(vab, w2);       // (w a, w b)
                    hAB2 = fma2(t1, vab, hAB2);         // (Sa2, Sb2)
                    hFF  = fma2(rfq[j], w2, hFF);       // (Sf, Sf2)
                    hABF = fma2(raf[j], w2, hABF);      // (Saf, Sbf)
                }
                // vertical scatter into 11 pending outputs (static slots)
#pragma unroll
                for (int j = 0; j < 11; ++j) {
                    const int s  = (p + 6 + j) % 11;
                    const u64 w2 = W2[j < 6 ? j : 10 - j];
                    aAB [s] = fma2(hAB , w2, aAB [s]);
                    aAB2[s] = fma2(hAB2, w2, aAB2[s]);
                    aABF[s] = fma2(hABF, w2, aABF[s]);
                    aFF [s] = fma2(hFF , w2, aFF [s]);
                }
            }

            // output row o = row - 5 completes in slot (p+6)%11 — scalar epilogue
            {
                const int o  = row - HALO;
                const int sd = (p + 6) % 11;
                if (o >= y0 && o < y1) {
                    float muA, muB, EA2, EB2, EAF, EBF, muF, EF2;
                    upk(aAB [sd], muA, muB);
                    upk(aAB2[sd], EA2, EB2);
                    upk(aABF[sd], EAF, EBF);
                    upk(aFF [sd], muF, EF2);
                    const float muF2 = muF * muF;
                    const float mc   = muF2 + C1;            // mu2^2 + C1 (shared)
                    const float s2   = (EF2 - muF2) + C2;    // sigma2 + C2 (shared)
                    float nA, dA, nB, dB;
                    {   // pair (A, F)
                        const float m12 = muA * muF;
                        const float mus = muA * muA;
                        nA = fmaf(2.0f, m12, C1) * fmaf(2.0f, EAF - m12, C2);
                        dA = (mus + mc) * ((EA2 - mus) + s2);
                    }
                    {   // pair (B, F)
                        const float m12 = muB * muF;
                        const float mus = muB * muB;
                        nB = fmaf(2.0f, m12, C1) * fmaf(2.0f, EBF - m12, C2);
                        dB = (mus + mc) * ((EB2 - mus) + s2);
                    }
                    // one MUFU: ssimA + ssimB = (nA*dB + nB*dA) / (dA*dB)
                    ssum += __fdividef(fmaf(nA, dB, nB * dA), dA * dB);
                }
                aAB[sd] = 0; aAB2[sd] = 0; aABF[sd] = 0; aFF[sd] = 0;
            }

            // stage prefetched row into next buffer, same phase slot
            sAB[IDX(nb, p, t)] = pk(va, vb);
            sFQ[IDX(nb, p, t)] = pk(vf, vf * vf);
            sAF[IDX(nb, p, t)] = pk(va * vf, vb * vf);
            if (t < 10) {
                sAB[IDX(nb, p, t + 128)] = pk(ua, ub);
                sFQ[IDX(nb, p, t + 128)] = pk(uf, uf * uf);
                sAF[IDX(nb, p, t + 128)] = pk(ua * uf, ub * uf);
            }
        }
        __syncthreads();
    }

    // block reduction -> single atomic per block
    const unsigned lane = t & 31u;
    const unsigned wid  = (unsigned)t >> 5;
#pragma unroll
    for (int off = 16; off; off >>= 1)
        ssum += __shfl_down_sync(0xffffffffu, ssum, off);
    if (lane == 0) wpart[wid] = ssum;
    __syncthreads();
    if (t == 0)
        atomicAdd(out, (wpart[0] + wpart[1] + wpart[2] + wpart[3]) * scale);
}

__global__ void zero_kernel(float* out) { *out = 0.0f; }

#define SMEM_BYTES (6 * NROW * 8 + 32)

extern "C" void kernel_launch(void* const* d_in, const int* in_sizes, int n_in,
                              void* d_out, int out_size)
{
    const float* A = (const float*)d_in[0];
    const float* B = (const float*)d_in[1];
    const float* F = (const float*)d_in[2];
    float* out = (float*)d_out;

    const int nplanes = in_sizes[0] / (IMG * IMG);   // 48
    const float scale = 0.5f / (float)in_sizes[0];

    cudaFuncSetAttribute(ssim_fused_kernel,
                         cudaFuncAttributeMaxDynamicSharedMemorySize, SMEM_BYTES);

    zero_kernel<<<1, 1>>>(out);
    dim3 grid(IMG / WSTRIP, IMG / HSEG, nplanes);
    ssim_fused_kernel<<<grid, 128, SMEM_BYTES>>>(A, B, F, out, scale);
}

// round 6
// speedup vs baseline: 1.1688x; 1.1688x over previous
#include <cuda_runtime.h>

#define IMG     512
#define WSTRIP  128
#define HSEG    128
#define HALO    5
#define SROW    138

typedef unsigned long long u64;

static __device__ __forceinline__ u64 pk(float lo, float hi) {
    u64 r; asm("mov.b64 %0, {%1, %2};" : "=l"(r) : "f"(lo), "f"(hi)); return r;
}
static __device__ __forceinline__ void upk(u64 v, float& lo, float& hi) {
    asm("mov.b64 {%0, %1}, %2;" : "=f"(lo), "=f"(hi) : "l"(v));
}
static __device__ __forceinline__ u64 fma2(u64 a, u64 b, u64 c) {
    u64 d; asm("fma.rn.f32x2 %0, %1, %2, %3;" : "=l"(d) : "l"(a), "l"(b), "l"(c)); return d;
}
static __device__ __forceinline__ u64 mul2(u64 a, u64 b) {
    u64 d; asm("mul.rn.f32x2 %0, %1, %2;" : "=l"(d) : "l"(a), "l"(b)); return d;
}

// Load one global row (zero-filled out of bounds) into a register stage set.
#define LOADSTAGE(PA, PB, PF, QA, QB, QF, R) do {                            \
    const int _r = (R);                                                      \
    PA = 0.f; PB = 0.f; PF = 0.f; QA = 0.f; QB = 0.f; QF = 0.f;              \
    if (_r >= ract_lo && _r <= ract_hi) {                                    \
        if (c0v) { const int _i = _r * IMG + c0; PA = ga[_i]; PB = gb[_i]; PF = gf[_i]; } \
        if (c1v) { const int _i = _r * IMG + c1; QA = ga[_i]; QB = gb[_i]; QF = gf[_i]; } \
    }                                                                        \
} while (0)

// Store a staged row (packed) into smem buffer NB, slot P.
#define STSTAGE(PA, PB, PF, QA, QB, QF, NB, P) do {                          \
    sAB[NB][P][t] = pk(PA, PB);                                              \
    sFQ[NB][P][t] = pk(PF, (PF) * (PF));                                     \
    if (t < 10) {                                                            \
        sAB[NB][P][t + 128] = pk(QA, QB);                                    \
        sFQ[NB][P][t + 128] = pk(QF, (QF) * (QF));                           \
    }                                                                        \
} while (0)

__global__ void __launch_bounds__(128, 3)
ssim_fused_kernel(const float* __restrict__ A, const float* __restrict__ B,
                  const float* __restrict__ F, float* __restrict__ out,
                  float scale)
{
    constexpr float W[11] = {0.00102838f, 0.00759876f, 0.03600077f, 0.10936069f,
                             0.21300553f, 0.26601172f, 0.21300553f, 0.10936069f,
                             0.03600077f, 0.00759876f, 0.00102838f};
    constexpr float C1 = 0.0001f, C2 = 0.0009f;

    const int t  = threadIdx.x;
    const int x0 = blockIdx.x * WSTRIP;
    const int y0 = blockIdx.y * HSEG;
    const int y1 = y0 + HSEG;
    const size_t poff = (size_t)blockIdx.z * (size_t)(IMG * IMG);
    const float* ga = A + poff;
    const float* gb = B + poff;
    const float* gf = F + poff;

    // double-buffered 11-row chunks; pre-packed channels:
    //   sAB[.][.][c] = (a, b)   sFQ[.][.][c] = (f, f*f)
    __shared__ u64 sAB[2][11][SROW];
    __shared__ u64 sFQ[2][11][SROW];
    __shared__ float wpart[4];

    u64 W2[6];
#pragma unroll
    for (int j = 0; j < 6; ++j) W2[j] = pk(W[j], W[j]);

    // vertical ring: 4 packed channels x 11 pending output rows
    u64 aAB[11], aAB2[11], aABF[11], aFF[11];
#pragma unroll
    for (int s = 0; s < 11; ++s) { aAB[s] = 0; aAB2[s] = 0; aABF[s] = 0; aFF[s] = 0; }

    float ssum = 0.0f;

    const int ract_lo = (y0 - HALO) < 0 ? 0 : (y0 - HALO);
    const int ract_hi = (y1 + HALO - 1) > (IMG - 1) ? (IMG - 1) : (y1 + HALO - 1);

    const int  c0  = x0 - HALO + t;
    const bool c0v = (c0 >= 0) && (c0 < IMG);
    const int  c1  = c0 + 128;
    const bool c1v = (t < 10) && (c1 < IMG);

    const int base    = ((y0 - HALO + 11) / 11) * 11 - 11;   // multiple of 11 <= y0-5
    const int nchunks = (y1 + HALO - base + 10) / 11;

    // ---- prologue: stage rows base..base+10 into buffer 0 ----
#pragma unroll
    for (int p = 0; p < 11; ++p) {
        const int r = base + p;
        float va = 0, vb = 0, vf = 0, ua = 0, ub = 0, uf = 0;
        if (r >= ract_lo && r <= ract_hi) {
            if (c0v) { const int i = r * IMG + c0; va = ga[i]; vb = gb[i]; vf = gf[i]; }
            if (c1v) { const int i = r * IMG + c1; ua = ga[i]; ub = gb[i]; uf = gf[i]; }
        }
        sAB[0][p][t] = pk(va, vb);
        sFQ[0][p][t] = pk(vf, vf * vf);
        if (t < 10) {
            sAB[0][p][t + 128] = pk(ua, ub);
            sFQ[0][p][t + 128] = pk(uf, uf * uf);
        }
    }

    // stage sets: S0 holds row base+11 (STS'd at phase 0), S1 holds base+12
    float p0a, p0b, p0f, q0a, q0b, q0f;
    float p1a, p1b, p1f, q1a, q1b, q1f;
    LOADSTAGE(p0a, p0b, p0f, q0a, q0b, q0f, base + 11);
    LOADSTAGE(p1a, p1b, p1f, q1a, q1b, q1f, base + 12);
    __syncthreads();

#pragma unroll 1
    for (int chk = 0; chk < nchunks; ++chk) {
        const int rbase = base + chk * 11;
        const int bb = chk & 1, nb = bb ^ 1;
#pragma unroll
        for (int p = 0; p < 11; ++p) {
            const int row = rbase + p;

            // 1) STS the row loaded 2 phases ago (row rbase+11+p), then
            //    refill the freed stage with row rbase+13+p (2-phase cover).
            if ((p & 1) == 0) {
                STSTAGE(p0a, p0b, p0f, q0a, q0b, q0f, nb, p);
                LOADSTAGE(p0a, p0b, p0f, q0a, q0b, q0f, rbase + 13 + p);
            } else {
                STSTAGE(p1a, p1b, p1f, q1a, q1b, q1f, nb, p);
                LOADSTAGE(p1a, p1b, p1f, q1a, q1b, q1f, rbase + 13 + p);
            }

            // 2) horizontal conv + vertical scatter
            if (row >= ract_lo && row <= ract_hi) {
                const u64* rab = sAB[bb][p];
                const u64* rfq = sFQ[bb][p];
                u64 hAB = 0, hAB2 = 0, hABF = 0, hFF = 0;
#pragma unroll
                for (int j = 0; j < 11; ++j) {
                    const u64 w2  = W2[j < 6 ? j : 10 - j];
                    const u64 vab = rab[t + j];
                    const u64 pf  = rfq[t + j];
                    hAB  = fma2(vab, w2, hAB);         // (Sa, Sb)
                    const u64 t1 = mul2(vab, w2);      // (w a, w b)
                    hAB2 = fma2(t1, vab, hAB2);        // (Sa2, Sb2)
                    hFF  = fma2(pf, w2, hFF);          // (Sf, Sf2)
                    float fl, fh; upk(pf, fl, fh);
                    const u64 vff = pk(fl, fl);        // (f, f)
                    hABF = fma2(t1, vff, hABF);        // (Saf, Sbf)
                }
#pragma unroll
                for (int j = 0; j < 11; ++j) {
                    const int s  = (p + 6 + j) % 11;
                    const u64 w2 = W2[j < 6 ? j : 10 - j];
                    aAB [s] = fma2(hAB , w2, aAB [s]);
                    aAB2[s] = fma2(hAB2, w2, aAB2[s]);
                    aABF[s] = fma2(hABF, w2, aABF[s]);
                    aFF [s] = fma2(hFF , w2, aFF [s]);
                }
            }

            // 3) output row o = row - 5 completes in slot (p+6)%11
            {
                const int o  = row - HALO;
                const int sd = (p + 6) % 11;
                if (o >= y0 && o < y1) {
                    float muA, muB, EA2, EB2, EAF, EBF, muF, EF2;
                    upk(aAB [sd], muA, muB);
                    upk(aAB2[sd], EA2, EB2);
                    upk(aABF[sd], EAF, EBF);
                    upk(aFF [sd], muF, EF2);
                    const float muF2 = muF * muF;
                    const float mc   = muF2 + C1;            // mu2^2 + C1 (shared)
                    const float s2   = (EF2 - muF2) + C2;    // sigma2 + C2 (shared)
                    float nA, dA, nB, dB;
                    {
                        const float m12 = muA * muF;
                        const float mus = muA * muA;
                        nA = fmaf(2.0f, m12, C1) * fmaf(2.0f, EAF - m12, C2);
                        dA = (mus + mc) * ((EA2 - mus) + s2);
                    }
                    {
                        const float m12 = muB * muF;
                        const float mus = muB * muB;
                        nB = fmaf(2.0f, m12, C1) * fmaf(2.0f, EBF - m12, C2);
                        dB = (mus + mc) * ((EB2 - mus) + s2);
                    }
                    // one MUFU: ssimA + ssimB = (nA*dB + nB*dA) / (dA*dB)
                    ssum += __fdividef(fmaf(nA, dB, nB * dA), dA * dB);
                }
                aAB[sd] = 0; aAB2[sd] = 0; aABF[sd] = 0; aFF[sd] = 0;
            }
        }
        __syncthreads();
        // 11 (odd) phases per chunk -> swap stage sets to keep parity static
        { float x;
          x = p0a; p0a = p1a; p1a = x;
          x = p0b; p0b = p1b; p1b = x;
          x = p0f; p0f = p1f; p1f = x;
          x = q0a; q0a = q1a; q1a = x;
          x = q0b; q0b = q1b; q1b = x;
          x = q0f; q0f = q1f; q1f = x; }
    }

    // block reduction -> single atomic per block
    const unsigned lane = t & 31u;
    const unsigned wid  = (unsigned)t >> 5;
#pragma unroll
    for (int off = 16; off; off >>= 1)
        ssum += __shfl_down_sync(0xffffffffu, ssum, off);
    if (lane == 0) wpart[wid] = ssum;
    __syncthreads();
    if (t == 0)
        atomicAdd(out, (wpart[0] + wpart[1] + wpart[2] + wpart[3]) * scale);
}

__global__ void zero_kernel(float* out) { *out = 0.0f; }

extern "C" void kernel_launch(void* const* d_in, const int* in_sizes, int n_in,
                              void* d_out, int out_size)
{
    const float* A = (const float*)d_in[0];
    const float* B = (const float*)d_in[1];
    const float* F = (const float*)d_in[2];
    float* out = (float*)d_out;

    const int nplanes = in_sizes[0] / (IMG * IMG);   // 48
    const float scale = 0.5f / (float)in_sizes[0];

    zero_kernel<<<1, 1>>>(out);
    dim3 grid(IMG / WSTRIP, IMG / HSEG, nplanes);
    ssim_fused_kernel<<<grid, 128>>>(A, B, F, out, scale);
}